// round 5
// baseline (speedup 1.0000x reference)
#include <cuda_runtime.h>
#include <cuda_bf16.h>
#include <math.h>
#include <stdint.h>

#define NE 8
#define NH 1024
#define NI 2048
#define NT 2048
#define RS 80   // smem row stride (bytes): 20-word stride -> conflict-free ldmatrix

// Scratch (static __device__ — allocation-free per harness rules)
__device__ int   g_count[NE];
__device__ int   g_list[NE * NT];
__device__ float g_wt[NE * NT];
__device__ __nv_bfloat16 g_act_hi[(size_t)NE * NT * NI];
__device__ __nv_bfloat16 g_act_lo[(size_t)NE * NT * NI];
// pre-split operands (hi/lo bf16)
__device__ __nv_bfloat16 g_x_hi[(size_t)NT * NH],  g_x_lo[(size_t)NT * NH];
__device__ __nv_bfloat16 g_w1_hi[(size_t)NE * NI * NH], g_w1_lo[(size_t)NE * NI * NH];
__device__ __nv_bfloat16 g_w3_hi[(size_t)NE * NI * NH], g_w3_lo[(size_t)NE * NI * NH];
__device__ __nv_bfloat16 g_w2_hi[(size_t)NE * NH * NI], g_w2_lo[(size_t)NE * NH * NI];

// ---------------- helpers ----------------
__device__ __forceinline__ uint32_t smem_u32(const void* p) {
    uint32_t r;
    asm("{ .reg .u64 t; cvta.to.shared.u64 t, %1; cvt.u32.u64 %0, t; }" : "=r"(r) : "l"(p));
    return r;
}
__device__ __forceinline__ void ldm_x4(uint32_t a, uint32_t r[4]) {
    asm volatile("ldmatrix.sync.aligned.m8n8.x4.shared.b16 {%0,%1,%2,%3}, [%4];"
                 : "=r"(r[0]), "=r"(r[1]), "=r"(r[2]), "=r"(r[3]) : "r"(a));
}
__device__ __forceinline__ void mma16816(float d[4], const uint32_t a[4],
                                         uint32_t b0, uint32_t b1) {
    asm volatile("mma.sync.aligned.m16n8k16.row.col.f32.bf16.bf16.f32 "
                 "{%0,%1,%2,%3}, {%4,%5,%6,%7}, {%8,%9}, {%0,%1,%2,%3};"
                 : "+f"(d[0]), "+f"(d[1]), "+f"(d[2]), "+f"(d[3])
                 : "r"(a[0]), "r"(a[1]), "r"(a[2]), "r"(a[3]), "r"(b0), "r"(b1));
}
__device__ __forceinline__ uint32_t pk2(float a, float b) {
    __nv_bfloat162 t = __floats2bfloat162_rn(a, b);
    return *reinterpret_cast<uint32_t*>(&t);
}
__device__ __forceinline__ void split4(float4 v, uint32_t& h0, uint32_t& h1,
                                       uint32_t& l0, uint32_t& l1) {
    float hx = __bfloat162float(__float2bfloat16_rn(v.x));
    float hy = __bfloat162float(__float2bfloat16_rn(v.y));
    float hz = __bfloat162float(__float2bfloat16_rn(v.z));
    float hw = __bfloat162float(__float2bfloat16_rn(v.w));
    h0 = pk2(hx, hy); h1 = pk2(hz, hw);
    l0 = pk2(v.x - hx, v.y - hy); l1 = pk2(v.z - hz, v.w - hw);
}
__device__ __forceinline__ void cp_async16(uint32_t dst, const void* src, int srcbytes) {
    asm volatile("cp.async.cg.shared.global [%0], [%1], 16, %2;"
                 :: "r"(dst), "l"(src), "r"(srcbytes) : "memory");
}
#define CP_COMMIT() asm volatile("cp.async.commit_group;" ::: "memory")
#define CP_WAIT0()  asm volatile("cp.async.wait_group 0;" ::: "memory")
#define CP_WAIT1()  asm volatile("cp.async.wait_group 1;" ::: "memory")

// ---------------- split (fp32 -> bf16 hi/lo) ----------------
__global__ __launch_bounds__(256) void split_kernel(const float4* __restrict__ src,
                                                    int n4, int which) {
    int i = blockIdx.x * 256 + threadIdx.x;
    if (i >= n4) return;
    float4 v = __ldg(src + i);
    uint32_t h0, h1, l0, l1;
    split4(v, h0, h1, l0, l1);
    uint2* dh; uint2* dl;
    switch (which) {
        case 0:  dh = (uint2*)g_x_hi;  dl = (uint2*)g_x_lo;  break;
        case 1:  dh = (uint2*)g_w1_hi; dl = (uint2*)g_w1_lo; break;
        case 2:  dh = (uint2*)g_w3_hi; dl = (uint2*)g_w3_lo; break;
        default: dh = (uint2*)g_w2_hi; dl = (uint2*)g_w2_lo; break;
    }
    dh[i] = make_uint2(h0, h1);
    dl[i] = make_uint2(l0, l1);
}

// ---------------- router ----------------
__global__ void zero_counts_kernel() {
    if (threadIdx.x < NE) g_count[threadIdx.x] = 0;
}

__global__ __launch_bounds__(256) void router_kernel(const float* __restrict__ x,
                                                     const float* __restrict__ gw) {
    int warp = (blockIdx.x * blockDim.x + threadIdx.x) >> 5;
    int lane = threadIdx.x & 31;
    if (warp >= NT) return;
    const float* xr = x + (size_t)warp * NH;
    float xv[32];
#pragma unroll
    for (int j = 0; j < 32; j++) xv[j] = xr[j * 32 + lane];
    float logits[NE];
#pragma unroll
    for (int e = 0; e < NE; e++) {
        const float* g = gw + e * NH;
        float p = 0.f;
#pragma unroll
        for (int j = 0; j < 32; j++) p += xv[j] * g[j * 32 + lane];
#pragma unroll
        for (int o = 16; o > 0; o >>= 1) p += __shfl_xor_sync(0xffffffffu, p, o);
        logits[e] = p;
    }
    if (lane == 0) {
        int i1 = 0;
#pragma unroll
        for (int e = 1; e < NE; e++) if (logits[e] > logits[i1]) i1 = e;
        int i2 = (i1 == 0) ? 1 : 0;
#pragma unroll
        for (int e = 0; e < NE; e++) if (e != i1 && logits[e] > logits[i2]) i2 = e;
        float s2  = __expf(logits[i2] - logits[i1]);
        float inv = 1.f / (1.f + s2);
        int p0 = atomicAdd(&g_count[i1], 1);
        g_list[i1 * NT + p0] = warp;
        g_wt [i1 * NT + p0] = inv;
        int p1 = atomicAdd(&g_count[i2], 1);
        g_list[i2 * NT + p1] = warp;
        g_wt [i2 * NT + p1] = s2 * inv;
    }
}

// Stage layout gemm1 (per stage 40960): AH 0, AL 10240, B1H 20480, B1L 25600, B3H 30720, B3L 35840
// Stage layout gemm2 (per stage 40960): AH 0, AL 10240, BH 20480, BL 30720
#define STG 40960

// ---------------- GEMM1: act = silu(x*w1^T) * (x*w3^T) ----------------
// 512 threads, CTA 128(M)x64(N=i), K-chunk 32, 3-stage cp.async. Warps 4(M)x4(N), warp 32x16.
__global__ __launch_bounds__(512) void gemm1_mma(int dummy) {
    int e   = blockIdx.z;
    int n_e = g_count[e];
    int row0 = blockIdx.y * 128;
    if (row0 >= n_e) return;
    int col0 = blockIdx.x * 64;

    extern __shared__ __align__(128) char sm[];
    int* toks = (int*)sm;
    int tid = threadIdx.x, wid = tid >> 5, lane = tid & 31;
    if (tid < 128) toks[tid] = (row0 + tid < n_e) ? g_list[e * NT + row0 + tid] : -1;
    __syncthreads();
    uint32_t smb = smem_u32(sm) + 1024;

    // A cp slots: 1024 = 256 rows (128 hi + 128 lo) x 4 c16
    const __nv_bfloat16* aps[2]; int asz[2]; uint32_t adst[2];
#pragma unroll
    for (int j = 0; j < 2; j++) {
        int idx = j * 512 + tid, r = idx >> 2, c16 = idx & 3;
        int rr = r & 127;
        bool hi = r < 128;
        int t = toks[rr];
        asz[j] = (t >= 0) ? 16 : 0;
        aps[j] = (hi ? g_x_hi : g_x_lo) + (size_t)(t < 0 ? 0 : t) * NH + c16 * 8;
        adst[j] = (hi ? 0u : 10240u) + (uint32_t)(rr * RS + c16 * 16);
    }
    // B cp slots: 1024 = 4 kinds x 64 rows x 4 c16
    const __nv_bfloat16* bps[2]; uint32_t bdst[2];
#pragma unroll
    for (int j = 0; j < 2; j++) {
        int idx = j * 512 + tid;
        int kind = idx >> 8, rem = idx & 255, r = rem >> 2, c16 = rem & 3;
        const __nv_bfloat16* base =
            (kind == 0) ? g_w1_hi : (kind == 1) ? g_w1_lo : (kind == 2) ? g_w3_hi : g_w3_lo;
        bps[j] = base + (size_t)e * NI * NH + (size_t)(col0 + r) * NH + c16 * 8;
        bdst[j] = 20480u + (uint32_t)kind * 5120u + (uint32_t)(r * RS + c16 * 16);
    }

    auto issue = [&](int ck, uint32_t stg) {
        int ko = ck * 32;
#pragma unroll
        for (int j = 0; j < 2; j++) cp_async16(stg + adst[j], aps[j] + ko, asz[j]);
#pragma unroll
        for (int j = 0; j < 2; j++) cp_async16(stg + bdst[j], bps[j] + ko, 16);
        CP_COMMIT();
    };

    int m0 = (wid & 3) * 32, n0 = (wid >> 2) * 16;
    uint32_t a_off = (uint32_t)((m0 + (lane & 15)) * RS + ((lane >> 4) << 4));
    uint32_t b_off = (uint32_t)((n0 + (lane & 7) + ((lane >> 4) << 3)) * RS +
                                (((lane >> 3) & 1) << 4));

    float dg[2][2][4] = {}, du[2][2][4] = {};

    issue(0, smb);
    issue(1, smb + STG);

    const int NC = NH / 32;
#pragma unroll 1
    for (int c = 0; c < NC; c++) {
        if (c + 1 < NC) { CP_WAIT1(); } else { CP_WAIT0(); }
        __syncthreads();
        if (c + 2 < NC) issue(c + 2, smb + ((c + 2) % 3) * STG);
        uint32_t cur = smb + (c % 3) * STG;
#pragma unroll
        for (int s2 = 0; s2 < 2; s2++) {
            uint32_t Ah[2][4], Al[2][4];
#pragma unroll
            for (int mt = 0; mt < 2; mt++) {
                ldm_x4(cur + a_off + mt * 16 * RS + s2 * 32, Ah[mt]);
                ldm_x4(cur + 10240 + a_off + mt * 16 * RS + s2 * 32, Al[mt]);
            }
            uint32_t B1h[4], B1l[4], B3h[4], B3l[4];
            ldm_x4(cur + 20480 + b_off + s2 * 32, B1h);
            ldm_x4(cur + 25600 + b_off + s2 * 32, B1l);
            ldm_x4(cur + 30720 + b_off + s2 * 32, B3h);
            ldm_x4(cur + 35840 + b_off + s2 * 32, B3l);
#pragma unroll
            for (int mt = 0; mt < 2; mt++)
#pragma unroll
                for (int nt = 0; nt < 2; nt++) {
                    int o = nt * 2;
                    mma16816(dg[mt][nt], Ah[mt], B1h[o], B1h[o + 1]);
                    mma16816(dg[mt][nt], Ah[mt], B1l[o], B1l[o + 1]);
                    mma16816(dg[mt][nt], Al[mt], B1h[o], B1h[o + 1]);
                    mma16816(du[mt][nt], Ah[mt], B3h[o], B3h[o + 1]);
                    mma16816(du[mt][nt], Ah[mt], B3l[o], B3l[o + 1]);
                    mma16816(du[mt][nt], Al[mt], B3h[o], B3h[o + 1]);
                }
        }
    }

    // epilogue: silu(g)*u, split to bf16 hi/lo
    int lr = lane >> 2, lc = lane & 3;
#pragma unroll
    for (int mt = 0; mt < 2; mt++)
#pragma unroll
        for (int p = 0; p < 2; p++) {
            int m = m0 + mt * 16 + lr + p * 8;
            int slot = row0 + m;
            if (slot < n_e) {
#pragma unroll
                for (int nt = 0; nt < 2; nt++) {
                    int n = col0 + n0 + nt * 8 + lc * 2;
                    float g0 = dg[mt][nt][2 * p], g1 = dg[mt][nt][2 * p + 1];
                    float u0 = du[mt][nt][2 * p], u1 = du[mt][nt][2 * p + 1];
                    float a0 = u0 * g0 / (1.f + __expf(-g0));
                    float a1 = u1 * g1 / (1.f + __expf(-g1));
                    __nv_bfloat16 h0 = __float2bfloat16_rn(a0);
                    __nv_bfloat16 h1 = __float2bfloat16_rn(a1);
                    __nv_bfloat162 hp; hp.x = h0; hp.y = h1;
                    size_t o = ((size_t)e * NT + slot) * NI + n;
                    *(uint32_t*)(g_act_hi + o) = *reinterpret_cast<uint32_t*>(&hp);
                    *(uint32_t*)(g_act_lo + o) =
                        pk2(a0 - __bfloat162float(h0), a1 - __bfloat162float(h1));
                }
            }
        }
}

// ---------------- GEMM2: out += route_w * (act * w2^T) ----------------
// 512 threads, CTA 128(M)x128(N=h), K-chunk 32, 3-stage cp.async. Warps 4(M)x4(N), warp 32x32.
__global__ __launch_bounds__(512) void gemm2_mma(float* __restrict__ out) {
    int e   = blockIdx.z;
    int n_e = g_count[e];
    int row0 = blockIdx.y * 128;
    if (row0 >= n_e) return;
    int col0 = blockIdx.x * 128;

    extern __shared__ __align__(128) char sm[];
    int*   toks = (int*)sm;
    float* wts  = (float*)(sm + 512);
    int tid = threadIdx.x, wid = tid >> 5, lane = tid & 31;
    if (tid < 128) {
        int slot = row0 + tid;
        toks[tid] = (slot < n_e) ? g_list[e * NT + slot] : 0;
        wts[tid]  = (slot < n_e) ? g_wt [e * NT + slot] : 0.f;
    }
    __syncthreads();
    uint32_t smb = smem_u32(sm) + 1024;

    // A cp slots: 1024 = 256 rows (128 hi + 128 lo) x 4 c16 (act gather)
    const __nv_bfloat16* aps[2]; int asz[2]; uint32_t adst[2];
#pragma unroll
    for (int j = 0; j < 2; j++) {
        int idx = j * 512 + tid, r = idx >> 2, c16 = idx & 3;
        int rr = r & 127;
        bool hi = r < 128;
        int slot = row0 + rr;
        bool v = slot < n_e;
        aps[j] = (hi ? g_act_hi : g_act_lo) + ((size_t)e * NT + (v ? slot : 0)) * NI + c16 * 8;
        asz[j] = v ? 16 : 0;
        adst[j] = (hi ? 0u : 10240u) + (uint32_t)(rr * RS + c16 * 16);
    }
    // B cp slots: 1024 = 256 rows (128 hi + 128 lo) x 4 c16 (w2)
    const __nv_bfloat16* bps[2]; uint32_t bdst[2];
#pragma unroll
    for (int j = 0; j < 2; j++) {
        int idx = j * 512 + tid, r = idx >> 2, c16 = idx & 3;
        int rr = r & 127;
        bool hi = r < 128;
        bps[j] = (hi ? g_w2_hi : g_w2_lo) + (size_t)e * NH * NI + (size_t)(col0 + rr) * NI + c16 * 8;
        bdst[j] = 20480u + (hi ? 0u : 10240u) + (uint32_t)(rr * RS + c16 * 16);
    }

    auto issue = [&](int ck, uint32_t stg) {
        int ko = ck * 32;
#pragma unroll
        for (int j = 0; j < 2; j++) cp_async16(stg + adst[j], aps[j] + ko, asz[j]);
#pragma unroll
        for (int j = 0; j < 2; j++) cp_async16(stg + bdst[j], bps[j] + ko, 16);
        CP_COMMIT();
    };

    int m0 = (wid & 3) * 32, n0 = (wid >> 2) * 32;
    uint32_t a_off = (uint32_t)((m0 + (lane & 15)) * RS + ((lane >> 4) << 4));
    uint32_t b_off = (uint32_t)((n0 + (lane & 7) + ((lane >> 4) << 3)) * RS +
                                (((lane >> 3) & 1) << 4));

    float d[2][4][4] = {};

    issue(0, smb);
    issue(1, smb + STG);

    const int NC = NI / 32;
#pragma unroll 1
    for (int c = 0; c < NC; c++) {
        if (c + 1 < NC) { CP_WAIT1(); } else { CP_WAIT0(); }
        __syncthreads();
        if (c + 2 < NC) issue(c + 2, smb + ((c + 2) % 3) * STG);
        uint32_t cur = smb + (c % 3) * STG;
#pragma unroll
        for (int s2 = 0; s2 < 2; s2++) {
            uint32_t Ah[2][4], Al[2][4];
#pragma unroll
            for (int mt = 0; mt < 2; mt++) {
                ldm_x4(cur + a_off + mt * 16 * RS + s2 * 32, Ah[mt]);
                ldm_x4(cur + 10240 + a_off + mt * 16 * RS + s2 * 32, Al[mt]);
            }
            uint32_t Bh[2][4], Bl[2][4];
#pragma unroll
            for (int j = 0; j < 2; j++) {
                ldm_x4(cur + 20480 + b_off + j * 16 * RS + s2 * 32, Bh[j]);
                ldm_x4(cur + 30720 + b_off + j * 16 * RS + s2 * 32, Bl[j]);
            }
#pragma unroll
            for (int mt = 0; mt < 2; mt++)
#pragma unroll
                for (int nt = 0; nt < 4; nt++) {
                    int j = nt >> 1, o = (nt & 1) * 2;
                    mma16816(d[mt][nt], Ah[mt], Bh[j][o], Bh[j][o + 1]);
                    mma16816(d[mt][nt], Ah[mt], Bl[j][o], Bl[j][o + 1]);
                    mma16816(d[mt][nt], Al[mt], Bh[j][o], Bh[j][o + 1]);
                }
        }
    }

    int lr = lane >> 2, lc = lane & 3;
#pragma unroll
    for (int mt = 0; mt < 2; mt++)
#pragma unroll
        for (int p = 0; p < 2; p++) {
            int m = m0 + mt * 16 + lr + p * 8;
            int slot = row0 + m;
            if (slot < n_e) {
                int   t = toks[m];
                float w = wts[m];
                float* dst = out + (size_t)t * NH;
#pragma unroll
                for (int nt = 0; nt < 4; nt++) {
                    int n = col0 + n0 + nt * 8 + lc * 2;
                    atomicAdd(dst + n,     w * d[mt][nt][2 * p]);
                    atomicAdd(dst + n + 1, w * d[mt][nt][2 * p + 1]);
                }
            }
        }
}

// ---------------- launch ----------------
extern "C" void kernel_launch(void* const* d_in, const int* in_sizes, int n_in,
                              void* d_out, int out_size) {
    const float* x  = (const float*)d_in[0];
    const float* gw = (const float*)d_in[1];
    const float* w1 = (const float*)d_in[2];
    const float* w3 = (const float*)d_in[3];
    const float* w2 = (const float*)d_in[4];
    float* out = (float*)d_out;

    const int SMEM = 1024 + 3 * STG;   // 123904
    cudaFuncSetAttribute(gemm1_mma, cudaFuncAttributeMaxDynamicSharedMemorySize, SMEM);
    cudaFuncSetAttribute(gemm2_mma, cudaFuncAttributeMaxDynamicSharedMemorySize, SMEM);

    cudaMemsetAsync(out, 0, (size_t)out_size * sizeof(float), 0);
    zero_counts_kernel<<<1, 32>>>();
    router_kernel<<<(NT * 32 + 255) / 256, 256>>>(x, gw);

    // pre-split operands into bf16 hi/lo
    const int n4x = NT * NH / 4;         // 524288
    const int n4w = NE * NI * NH / 4;    // 4194304
    split_kernel<<<(n4x + 255) / 256, 256>>>((const float4*)x,  n4x, 0);
    split_kernel<<<(n4w + 255) / 256, 256>>>((const float4*)w1, n4w, 1);
    split_kernel<<<(n4w + 255) / 256, 256>>>((const float4*)w3, n4w, 2);
    split_kernel<<<(n4w + 255) / 256, 256>>>((const float4*)w2, n4w, 3);

    dim3 grid1(NI / 64, NT / 128, NE);
    gemm1_mma<<<grid1, 512, SMEM>>>(0);

    dim3 grid2(NH / 128, NT / 128, NE);
    gemm2_mma<<<grid2, 512, SMEM>>>(out);
}

// round 6
// speedup vs baseline: 1.1022x; 1.1022x over previous
#include <cuda_runtime.h>
#include <cuda_bf16.h>
#include <math.h>
#include <stdint.h>

#define NE 8
#define NH 1024
#define NI 2048
#define NT 2048
#define RS 80   // smem row stride (bytes): 20-word stride -> conflict-free ldmatrix

// Scratch (static __device__ — allocation-free per harness rules)
__device__ int   g_count[NE];
__device__ int   g_list[NE * NT];
__device__ float g_wt[NE * NT];
__device__ __nv_bfloat16 g_act_hi[(size_t)NE * NT * NI];
__device__ __nv_bfloat16 g_act_lo[(size_t)NE * NT * NI];
// pre-split operands (hi/lo bf16)
__device__ __nv_bfloat16 g_x_hi[(size_t)NT * NH],  g_x_lo[(size_t)NT * NH];
__device__ __nv_bfloat16 g_w1_hi[(size_t)NE * NI * NH], g_w1_lo[(size_t)NE * NI * NH];
__device__ __nv_bfloat16 g_w3_hi[(size_t)NE * NI * NH], g_w3_lo[(size_t)NE * NI * NH];
__device__ __nv_bfloat16 g_w2_hi[(size_t)NE * NH * NI], g_w2_lo[(size_t)NE * NH * NI];

// ---------------- helpers ----------------
__device__ __forceinline__ uint32_t smem_u32(const void* p) {
    uint32_t r;
    asm("{ .reg .u64 t; cvta.to.shared.u64 t, %1; cvt.u32.u64 %0, t; }" : "=r"(r) : "l"(p));
    return r;
}
__device__ __forceinline__ void ldm_x4(uint32_t a, uint32_t r[4]) {
    asm volatile("ldmatrix.sync.aligned.m8n8.x4.shared.b16 {%0,%1,%2,%3}, [%4];"
                 : "=r"(r[0]), "=r"(r[1]), "=r"(r[2]), "=r"(r[3]) : "r"(a));
}
__device__ __forceinline__ void mma16816(float d[4], const uint32_t a[4],
                                         uint32_t b0, uint32_t b1) {
    asm volatile("mma.sync.aligned.m16n8k16.row.col.f32.bf16.bf16.f32 "
                 "{%0,%1,%2,%3}, {%4,%5,%6,%7}, {%8,%9}, {%0,%1,%2,%3};"
                 : "+f"(d[0]), "+f"(d[1]), "+f"(d[2]), "+f"(d[3])
                 : "r"(a[0]), "r"(a[1]), "r"(a[2]), "r"(a[3]), "r"(b0), "r"(b1));
}
__device__ __forceinline__ uint32_t pk2(float a, float b) {
    __nv_bfloat162 t = __floats2bfloat162_rn(a, b);
    return *reinterpret_cast<uint32_t*>(&t);
}
__device__ __forceinline__ void split4(float4 v, uint32_t& h0, uint32_t& h1,
                                       uint32_t& l0, uint32_t& l1) {
    float hx = __bfloat162float(__float2bfloat16_rn(v.x));
    float hy = __bfloat162float(__float2bfloat16_rn(v.y));
    float hz = __bfloat162float(__float2bfloat16_rn(v.z));
    float hw = __bfloat162float(__float2bfloat16_rn(v.w));
    h0 = pk2(hx, hy); h1 = pk2(hz, hw);
    l0 = pk2(v.x - hx, v.y - hy); l1 = pk2(v.z - hz, v.w - hw);
}
__device__ __forceinline__ void cp_async16(uint32_t dst, const void* src, int srcbytes) {
    asm volatile("cp.async.cg.shared.global [%0], [%1], 16, %2;"
                 :: "r"(dst), "l"(src), "r"(srcbytes) : "memory");
}
#define CP_COMMIT() asm volatile("cp.async.commit_group;" ::: "memory")
#define CP_WAIT0()  asm volatile("cp.async.wait_group 0;" ::: "memory")
#define CP_WAIT1()  asm volatile("cp.async.wait_group 1;" ::: "memory")

// ---------------- split (fp32 -> bf16 hi/lo) ----------------
__global__ __launch_bounds__(256) void split_kernel(const float4* __restrict__ src,
                                                    int n4, int which) {
    int i = blockIdx.x * 256 + threadIdx.x;
    if (i >= n4) return;
    float4 v = __ldg(src + i);
    uint32_t h0, h1, l0, l1;
    split4(v, h0, h1, l0, l1);
    uint2* dh; uint2* dl;
    switch (which) {
        case 0:  dh = (uint2*)g_x_hi;  dl = (uint2*)g_x_lo;  break;
        case 1:  dh = (uint2*)g_w1_hi; dl = (uint2*)g_w1_lo; break;
        case 2:  dh = (uint2*)g_w3_hi; dl = (uint2*)g_w3_lo; break;
        default: dh = (uint2*)g_w2_hi; dl = (uint2*)g_w2_lo; break;
    }
    dh[i] = make_uint2(h0, h1);
    dl[i] = make_uint2(l0, l1);
}

// ---------------- router ----------------
__global__ void zero_counts_kernel() {
    if (threadIdx.x < NE) g_count[threadIdx.x] = 0;
}

__global__ __launch_bounds__(256) void router_kernel(const float* __restrict__ x,
                                                     const float* __restrict__ gw) {
    int warp = (blockIdx.x * blockDim.x + threadIdx.x) >> 5;
    int lane = threadIdx.x & 31;
    if (warp >= NT) return;
    const float* xr = x + (size_t)warp * NH;
    float xv[32];
#pragma unroll
    for (int j = 0; j < 32; j++) xv[j] = xr[j * 32 + lane];
    float logits[NE];
#pragma unroll
    for (int e = 0; e < NE; e++) {
        const float* g = gw + e * NH;
        float p = 0.f;
#pragma unroll
        for (int j = 0; j < 32; j++) p += xv[j] * g[j * 32 + lane];
#pragma unroll
        for (int o = 16; o > 0; o >>= 1) p += __shfl_xor_sync(0xffffffffu, p, o);
        logits[e] = p;
    }
    if (lane == 0) {
        int i1 = 0;
#pragma unroll
        for (int e = 1; e < NE; e++) if (logits[e] > logits[i1]) i1 = e;
        int i2 = (i1 == 0) ? 1 : 0;
#pragma unroll
        for (int e = 0; e < NE; e++) if (e != i1 && logits[e] > logits[i2]) i2 = e;
        float s2  = __expf(logits[i2] - logits[i1]);
        float inv = 1.f / (1.f + s2);
        int p0 = atomicAdd(&g_count[i1], 1);
        g_list[i1 * NT + p0] = warp;
        g_wt [i1 * NT + p0] = inv;
        int p1 = atomicAdd(&g_count[i2], 1);
        g_list[i2 * NT + p1] = warp;
        g_wt [i2 * NT + p1] = s2 * inv;
    }
}

// Stage layouts (per stage 40960 bytes):
//  gemm1: AH 0, AL 10240, B1H 20480, B1L 25600, B3H 30720, B3L 35840
//  gemm2: AH 0, AL 10240, BH 20480, BL 30720
#define STG 40960

// ---------------- GEMM1: act = silu(x*w1^T) * (x*w3^T) ----------------
// 256 thr, 2 CTAs/SM. CTA 128(M)x64(N=i), K-chunk 32, 2-stage cp.async.
// Warps 4(M)x2(N), warp 32x32 for BOTH g and u.
__global__ __launch_bounds__(256, 2) void gemm1_mma(int dummy) {
    int e   = blockIdx.z;
    int n_e = g_count[e];
    int row0 = blockIdx.y * 128;
    if (row0 >= n_e) return;
    int col0 = blockIdx.x * 64;

    extern __shared__ __align__(128) char sm[];
    int* toks = (int*)sm;
    int tid = threadIdx.x, wid = tid >> 5, lane = tid & 31;
    if (tid < 128) toks[tid] = (row0 + tid < n_e) ? g_list[e * NT + row0 + tid] : -1;
    __syncthreads();
    uint32_t smb = smem_u32(sm) + 1024;

    // A cp slots: 1024 = 256 rows (128 hi + 128 lo) x 4 c16 -> 4 per thread
    const __nv_bfloat16* aps[4]; int asz[4]; uint32_t adst[4];
#pragma unroll
    for (int j = 0; j < 4; j++) {
        int idx = j * 256 + tid, r = idx >> 2, c16 = idx & 3;
        int rr = r & 127;
        bool hi = r < 128;
        int t = toks[rr];
        asz[j] = (t >= 0) ? 16 : 0;
        aps[j] = (hi ? g_x_hi : g_x_lo) + (size_t)(t < 0 ? 0 : t) * NH + c16 * 8;
        adst[j] = (hi ? 0u : 10240u) + (uint32_t)(rr * RS + c16 * 16);
    }
    // B cp slots: 1024 = 4 kinds x 64 rows x 4 c16 -> 4 per thread
    const __nv_bfloat16* bps[4]; uint32_t bdst[4];
#pragma unroll
    for (int j = 0; j < 4; j++) {
        int idx = j * 256 + tid;
        int kind = idx >> 8, rem = idx & 255, r = rem >> 2, c16 = rem & 3;
        const __nv_bfloat16* base =
            (kind == 0) ? g_w1_hi : (kind == 1) ? g_w1_lo : (kind == 2) ? g_w3_hi : g_w3_lo;
        bps[j] = base + (size_t)e * NI * NH + (size_t)(col0 + r) * NH + c16 * 8;
        bdst[j] = 20480u + (uint32_t)kind * 5120u + (uint32_t)(r * RS + c16 * 16);
    }

    auto issue = [&](int ck) {
        uint32_t stg = smb + (ck & 1) * STG;
        int ko = ck * 32;
#pragma unroll
        for (int j = 0; j < 4; j++) cp_async16(stg + adst[j], aps[j] + ko, asz[j]);
#pragma unroll
        for (int j = 0; j < 4; j++) cp_async16(stg + bdst[j], bps[j] + ko, 16);
        CP_COMMIT();
    };

    int m0 = (wid & 3) * 32, n0 = (wid >> 2) * 32;
    uint32_t a_off = (uint32_t)((m0 + (lane & 15)) * RS + ((lane >> 4) << 4));
    uint32_t b_off = (uint32_t)((n0 + (lane & 7) + ((lane >> 4) << 3)) * RS +
                                (((lane >> 3) & 1) << 4));

    float dg[2][4][4] = {}, du[2][4][4] = {};

    issue(0);

    const int NC = NH / 32;
#pragma unroll 1
    for (int c = 0; c < NC; c++) {
        if (c + 1 < NC) { issue(c + 1); CP_WAIT1(); } else { CP_WAIT0(); }
        __syncthreads();
        uint32_t cur = smb + (c & 1) * STG;
#pragma unroll
        for (int s2 = 0; s2 < 2; s2++) {
            uint32_t Ah[2][4], Al[2][4];
#pragma unroll
            for (int mt = 0; mt < 2; mt++) {
                ldm_x4(cur + a_off + mt * 16 * RS + s2 * 32, Ah[mt]);
                ldm_x4(cur + 10240 + a_off + mt * 16 * RS + s2 * 32, Al[mt]);
            }
            {   // w1 -> dg
                uint32_t Bh[2][4], Bl[2][4];
#pragma unroll
                for (int j = 0; j < 2; j++) {
                    ldm_x4(cur + 20480 + b_off + j * 16 * RS + s2 * 32, Bh[j]);
                    ldm_x4(cur + 25600 + b_off + j * 16 * RS + s2 * 32, Bl[j]);
                }
#pragma unroll
                for (int mt = 0; mt < 2; mt++)
#pragma unroll
                    for (int nt = 0; nt < 4; nt++) {
                        int j = nt >> 1, o = (nt & 1) * 2;
                        mma16816(dg[mt][nt], Ah[mt], Bh[j][o], Bh[j][o + 1]);
                        mma16816(dg[mt][nt], Ah[mt], Bl[j][o], Bl[j][o + 1]);
                        mma16816(dg[mt][nt], Al[mt], Bh[j][o], Bh[j][o + 1]);
                    }
            }
            {   // w3 -> du
                uint32_t Bh[2][4], Bl[2][4];
#pragma unroll
                for (int j = 0; j < 2; j++) {
                    ldm_x4(cur + 30720 + b_off + j * 16 * RS + s2 * 32, Bh[j]);
                    ldm_x4(cur + 35840 + b_off + j * 16 * RS + s2 * 32, Bl[j]);
                }
#pragma unroll
                for (int mt = 0; mt < 2; mt++)
#pragma unroll
                    for (int nt = 0; nt < 4; nt++) {
                        int j = nt >> 1, o = (nt & 1) * 2;
                        mma16816(du[mt][nt], Ah[mt], Bh[j][o], Bh[j][o + 1]);
                        mma16816(du[mt][nt], Ah[mt], Bl[j][o], Bl[j][o + 1]);
                        mma16816(du[mt][nt], Al[mt], Bh[j][o], Bh[j][o + 1]);
                    }
            }
        }
        __syncthreads();
    }

    // epilogue: silu(g)*u, split to bf16 hi/lo
    int lr = lane >> 2, lc = lane & 3;
#pragma unroll
    for (int mt = 0; mt < 2; mt++)
#pragma unroll
        for (int p = 0; p < 2; p++) {
            int m = m0 + mt * 16 + lr + p * 8;
            int slot = row0 + m;
            if (slot < n_e) {
#pragma unroll
                for (int nt = 0; nt < 4; nt++) {
                    int n = col0 + n0 + nt * 8 + lc * 2;
                    float g0 = dg[mt][nt][2 * p], g1 = dg[mt][nt][2 * p + 1];
                    float u0 = du[mt][nt][2 * p], u1 = du[mt][nt][2 * p + 1];
                    float a0 = u0 * g0 / (1.f + __expf(-g0));
                    float a1 = u1 * g1 / (1.f + __expf(-g1));
                    __nv_bfloat16 h0 = __float2bfloat16_rn(a0);
                    __nv_bfloat16 h1 = __float2bfloat16_rn(a1);
                    __nv_bfloat162 hp; hp.x = h0; hp.y = h1;
                    size_t o = ((size_t)e * NT + slot) * NI + n;
                    *(uint32_t*)(g_act_hi + o) = *reinterpret_cast<uint32_t*>(&hp);
                    *(uint32_t*)(g_act_lo + o) =
                        pk2(a0 - __bfloat162float(h0), a1 - __bfloat162float(h1));
                }
            }
        }
}

// ---------------- GEMM2: out += route_w * (act * w2^T) ----------------
// 256 thr, 2 CTAs/SM. CTA 128(M)x128(N=h), K-chunk 32, 2-stage cp.async.
// Warps 4(M)x2(N), warp 32x64.
__global__ __launch_bounds__(256, 2) void gemm2_mma(float* __restrict__ out) {
    int e   = blockIdx.z;
    int n_e = g_count[e];
    int row0 = blockIdx.y * 128;
    if (row0 >= n_e) return;
    int col0 = blockIdx.x * 128;

    extern __shared__ __align__(128) char sm[];
    int*   toks = (int*)sm;
    float* wts  = (float*)(sm + 512);
    int tid = threadIdx.x, wid = tid >> 5, lane = tid & 31;
    if (tid < 128) {
        int slot = row0 + tid;
        toks[tid] = (slot < n_e) ? g_list[e * NT + slot] : 0;
        wts[tid]  = (slot < n_e) ? g_wt [e * NT + slot] : 0.f;
    }
    __syncthreads();
    uint32_t smb = smem_u32(sm) + 1024;

    // A cp slots (act gather): 1024 -> 4 per thread
    const __nv_bfloat16* aps[4]; int asz[4]; uint32_t adst[4];
#pragma unroll
    for (int j = 0; j < 4; j++) {
        int idx = j * 256 + tid, r = idx >> 2, c16 = idx & 3;
        int rr = r & 127;
        bool hi = r < 128;
        int slot = row0 + rr;
        bool v = slot < n_e;
        aps[j] = (hi ? g_act_hi : g_act_lo) + ((size_t)e * NT + (v ? slot : 0)) * NI + c16 * 8;
        asz[j] = v ? 16 : 0;
        adst[j] = (hi ? 0u : 10240u) + (uint32_t)(rr * RS + c16 * 16);
    }
    // B cp slots (w2): 1024 -> 4 per thread
    const __nv_bfloat16* bps[4]; uint32_t bdst[4];
#pragma unroll
    for (int j = 0; j < 4; j++) {
        int idx = j * 256 + tid, r = idx >> 2, c16 = idx & 3;
        int rr = r & 127;
        bool hi = r < 128;
        bps[j] = (hi ? g_w2_hi : g_w2_lo) + (size_t)e * NH * NI + (size_t)(col0 + rr) * NI + c16 * 8;
        bdst[j] = 20480u + (hi ? 0u : 10240u) + (uint32_t)(rr * RS + c16 * 16);
    }

    auto issue = [&](int ck) {
        uint32_t stg = smb + (ck & 1) * STG;
        int ko = ck * 32;
#pragma unroll
        for (int j = 0; j < 4; j++) cp_async16(stg + adst[j], aps[j] + ko, asz[j]);
#pragma unroll
        for (int j = 0; j < 4; j++) cp_async16(stg + bdst[j], bps[j] + ko, 16);
        CP_COMMIT();
    };

    int m0 = (wid & 3) * 32, n0 = (wid >> 2) * 64;
    uint32_t a_off = (uint32_t)((m0 + (lane & 15)) * RS + ((lane >> 4) << 4));
    uint32_t b_off = (uint32_t)((n0 + (lane & 7) + ((lane >> 4) << 3)) * RS +
                                (((lane >> 3) & 1) << 4));

    float d[2][8][4] = {};

    issue(0);

    const int NC = NI / 32;
#pragma unroll 1
    for (int c = 0; c < NC; c++) {
        if (c + 1 < NC) { issue(c + 1); CP_WAIT1(); } else { CP_WAIT0(); }
        __syncthreads();
        uint32_t cur = smb + (c & 1) * STG;
#pragma unroll
        for (int s2 = 0; s2 < 2; s2++) {
            uint32_t Ah[2][4], Al[2][4];
#pragma unroll
            for (int mt = 0; mt < 2; mt++) {
                ldm_x4(cur + a_off + mt * 16 * RS + s2 * 32, Ah[mt]);
                ldm_x4(cur + 10240 + a_off + mt * 16 * RS + s2 * 32, Al[mt]);
            }
#pragma unroll
            for (int j = 0; j < 4; j++) {
                uint32_t Bh[4], Bl[4];
                ldm_x4(cur + 20480 + b_off + j * 16 * RS + s2 * 32, Bh);
                ldm_x4(cur + 30720 + b_off + j * 16 * RS + s2 * 32, Bl);
#pragma unroll
                for (int mt = 0; mt < 2; mt++)
#pragma unroll
                    for (int nn = 0; nn < 2; nn++) {
                        int nt = j * 2 + nn, o = nn * 2;
                        mma16816(d[mt][nt], Ah[mt], Bh[o], Bh[o + 1]);
                        mma16816(d[mt][nt], Ah[mt], Bl[o], Bl[o + 1]);
                        mma16816(d[mt][nt], Al[mt], Bh[o], Bh[o + 1]);
                    }
            }
        }
        __syncthreads();
    }

    int lr = lane >> 2, lc = lane & 3;
#pragma unroll
    for (int mt = 0; mt < 2; mt++)
#pragma unroll
        for (int p = 0; p < 2; p++) {
            int m = m0 + mt * 16 + lr + p * 8;
            int slot = row0 + m;
            if (slot < n_e) {
                int   t = toks[m];
                float w = wts[m];
                float* dst = out + (size_t)t * NH;
#pragma unroll
                for (int nt = 0; nt < 8; nt++) {
                    int n = col0 + n0 + nt * 8 + lc * 2;
                    atomicAdd(dst + n,     w * d[mt][nt][2 * p]);
                    atomicAdd(dst + n + 1, w * d[mt][nt][2 * p + 1]);
                }
            }
        }
}

// ---------------- launch ----------------
extern "C" void kernel_launch(void* const* d_in, const int* in_sizes, int n_in,
                              void* d_out, int out_size) {
    const float* x  = (const float*)d_in[0];
    const float* gw = (const float*)d_in[1];
    const float* w1 = (const float*)d_in[2];
    const float* w3 = (const float*)d_in[3];
    const float* w2 = (const float*)d_in[4];
    float* out = (float*)d_out;

    const int SMEM = 1024 + 2 * STG;   // 82944 -> 2 CTAs/SM
    cudaFuncSetAttribute(gemm1_mma, cudaFuncAttributeMaxDynamicSharedMemorySize, SMEM);
    cudaFuncSetAttribute(gemm2_mma, cudaFuncAttributeMaxDynamicSharedMemorySize, SMEM);

    cudaMemsetAsync(out, 0, (size_t)out_size * sizeof(float), 0);
    zero_counts_kernel<<<1, 32>>>();
    router_kernel<<<(NT * 32 + 255) / 256, 256>>>(x, gw);

    // pre-split operands into bf16 hi/lo
    const int n4x = NT * NH / 4;         // 524288
    const int n4w = NE * NI * NH / 4;    // 4194304
    split_kernel<<<(n4x + 255) / 256, 256>>>((const float4*)x,  n4x, 0);
    split_kernel<<<(n4w + 255) / 256, 256>>>((const float4*)w1, n4w, 1);
    split_kernel<<<(n4w + 255) / 256, 256>>>((const float4*)w3, n4w, 2);
    split_kernel<<<(n4w + 255) / 256, 256>>>((const float4*)w2, n4w, 3);

    dim3 grid1(NI / 64, NT / 128, NE);
    gemm1_mma<<<grid1, 256, SMEM>>>(0);

    dim3 grid2(NH / 128, NT / 128, NE);
    gemm2_mma<<<grid2, 256, SMEM>>>(out);
}

// round 7
// speedup vs baseline: 1.1544x; 1.0473x over previous
#include <cuda_runtime.h>
#include <cuda_bf16.h>
#include <math.h>
#include <stdint.h>

#define NE 8
#define NH 1024
#define NI 2048
#define NT 2048
#define RS 80   // smem row stride (bytes): 20-word stride -> conflict-free ldmatrix

// Scratch (static __device__ — allocation-free per harness rules)
__device__ int   g_count[NE];
__device__ int   g_list[NE * NT];
__device__ float g_wt[NE * NT];
__device__ __nv_bfloat16 g_act_hi[(size_t)NE * NT * NI];
__device__ __nv_bfloat16 g_act_lo[(size_t)NE * NT * NI];
// pre-split operands (hi/lo bf16)
__device__ __nv_bfloat16 g_x_hi[(size_t)NT * NH],  g_x_lo[(size_t)NT * NH];
__device__ __nv_bfloat16 g_w1_hi[(size_t)NE * NI * NH], g_w1_lo[(size_t)NE * NI * NH];
__device__ __nv_bfloat16 g_w3_hi[(size_t)NE * NI * NH], g_w3_lo[(size_t)NE * NI * NH];
__device__ __nv_bfloat16 g_w2_hi[(size_t)NE * NH * NI], g_w2_lo[(size_t)NE * NH * NI];

// ---------------- helpers ----------------
__device__ __forceinline__ uint32_t smem_u32(const void* p) {
    uint32_t r;
    asm("{ .reg .u64 t; cvta.to.shared.u64 t, %1; cvt.u32.u64 %0, t; }" : "=r"(r) : "l"(p));
    return r;
}
__device__ __forceinline__ void ldm_x4(uint32_t a, uint32_t r[4]) {
    asm volatile("ldmatrix.sync.aligned.m8n8.x4.shared.b16 {%0,%1,%2,%3}, [%4];"
                 : "=r"(r[0]), "=r"(r[1]), "=r"(r[2]), "=r"(r[3]) : "r"(a));
}
__device__ __forceinline__ void mma16816(float d[4], const uint32_t a[4],
                                         uint32_t b0, uint32_t b1) {
    asm volatile("mma.sync.aligned.m16n8k16.row.col.f32.bf16.bf16.f32 "
                 "{%0,%1,%2,%3}, {%4,%5,%6,%7}, {%8,%9}, {%0,%1,%2,%3};"
                 : "+f"(d[0]), "+f"(d[1]), "+f"(d[2]), "+f"(d[3])
                 : "r"(a[0]), "r"(a[1]), "r"(a[2]), "r"(a[3]), "r"(b0), "r"(b1));
}
__device__ __forceinline__ uint32_t pk2(float a, float b) {
    __nv_bfloat162 t = __floats2bfloat162_rn(a, b);
    return *reinterpret_cast<uint32_t*>(&t);
}
__device__ __forceinline__ void split4(float4 v, uint32_t& h0, uint32_t& h1,
                                       uint32_t& l0, uint32_t& l1) {
    float hx = __bfloat162float(__float2bfloat16_rn(v.x));
    float hy = __bfloat162float(__float2bfloat16_rn(v.y));
    float hz = __bfloat162float(__float2bfloat16_rn(v.z));
    float hw = __bfloat162float(__float2bfloat16_rn(v.w));
    h0 = pk2(hx, hy); h1 = pk2(hz, hw);
    l0 = pk2(v.x - hx, v.y - hy); l1 = pk2(v.z - hz, v.w - hw);
}
__device__ __forceinline__ void cp_async16(uint32_t dst, const void* src, int srcbytes) {
    asm volatile("cp.async.cg.shared.global [%0], [%1], 16, %2;"
                 :: "r"(dst), "l"(src), "r"(srcbytes) : "memory");
}
#define CP_COMMIT() asm volatile("cp.async.commit_group;" ::: "memory")
#define CP_WAIT0()  asm volatile("cp.async.wait_group 0;" ::: "memory")

// ---------------- split kernels (fp32 -> bf16 hi/lo), 2x ILP ----------------
__global__ __launch_bounds__(256) void splitx_kernel(const float4* __restrict__ src) {
    int i = blockIdx.x * 512 + threadIdx.x;
    uint2* dh = (uint2*)g_x_hi; uint2* dl = (uint2*)g_x_lo;
#pragma unroll
    for (int k = 0; k < 2; k++) {
        int ii = i + k * 256;
        float4 v = __ldg(src + ii);
        uint32_t h0, h1, l0, l1;
        split4(v, h0, h1, l0, l1);
        dh[ii] = make_uint2(h0, h1);
        dl[ii] = make_uint2(l0, l1);
    }
}
__global__ __launch_bounds__(256) void splitw_kernel(const float4* __restrict__ w1,
                                                     const float4* __restrict__ w3,
                                                     const float4* __restrict__ w2) {
    int which = blockIdx.y;
    const float4* src = (which == 0) ? w1 : (which == 1) ? w3 : w2;
    uint2* dh = (which == 0) ? (uint2*)g_w1_hi : (which == 1) ? (uint2*)g_w3_hi : (uint2*)g_w2_hi;
    uint2* dl = (which == 0) ? (uint2*)g_w1_lo : (which == 1) ? (uint2*)g_w3_lo : (uint2*)g_w2_lo;
    int i = blockIdx.x * 512 + threadIdx.x;
#pragma unroll
    for (int k = 0; k < 2; k++) {
        int ii = i + k * 256;
        float4 v = __ldg(src + ii);
        uint32_t h0, h1, l0, l1;
        split4(v, h0, h1, l0, l1);
        dh[ii] = make_uint2(h0, h1);
        dl[ii] = make_uint2(l0, l1);
    }
}

// ---------------- router ----------------
__global__ void zero_counts_kernel() {
    if (threadIdx.x < NE) g_count[threadIdx.x] = 0;
}

__global__ __launch_bounds__(256) void router_kernel(const float* __restrict__ x,
                                                     const float* __restrict__ gw) {
    int warp = (blockIdx.x * blockDim.x + threadIdx.x) >> 5;
    int lane = threadIdx.x & 31;
    if (warp >= NT) return;
    const float* xr = x + (size_t)warp * NH;
    float xv[32];
#pragma unroll
    for (int j = 0; j < 32; j++) xv[j] = xr[j * 32 + lane];
    float logits[NE];
#pragma unroll
    for (int e = 0; e < NE; e++) {
        const float* g = gw + e * NH;
        float p = 0.f;
#pragma unroll
        for (int j = 0; j < 32; j++) p += xv[j] * g[j * 32 + lane];
#pragma unroll
        for (int o = 16; o > 0; o >>= 1) p += __shfl_xor_sync(0xffffffffu, p, o);
        logits[e] = p;
    }
    if (lane == 0) {
        int i1 = 0;
#pragma unroll
        for (int e = 1; e < NE; e++) if (logits[e] > logits[i1]) i1 = e;
        int i2 = (i1 == 0) ? 1 : 0;
#pragma unroll
        for (int e = 0; e < NE; e++) if (e != i1 && logits[e] > logits[i2]) i2 = e;
        float s2  = __expf(logits[i2] - logits[i1]);
        float inv = 1.f / (1.f + s2);
        int p0 = atomicAdd(&g_count[i1], 1);
        g_list[i1 * NT + p0] = warp;
        g_wt [i1 * NT + p0] = inv;
        int p1 = atomicAdd(&g_count[i2], 1);
        g_list[i2 * NT + p1] = warp;
        g_wt [i2 * NT + p1] = s2 * inv;
    }
}

// Stage layouts (per stage 40960 bytes):
//  gemm1: AH 0, AL 10240, B1H 20480, B1L 25600, B3H 30720, B3L 35840
//  gemm2: AH 0, AL 10240, BH 20480, BL 30720
#define STG 40960

// ---------------- GEMM1: act = silu(x*w1^T) * (x*w3^T) ----------------
// 256 thr, 2 CTAs/SM. CTA 128(M)x64(N=i), K-chunk 32, 2-stage cp.async, ONE barrier/chunk.
// Warps 4(M)x2(N), warp 32x32 for BOTH g and u.
__global__ __launch_bounds__(256, 2) void gemm1_mma(int dummy) {
    int e   = blockIdx.z;
    int n_e = g_count[e];
    int row0 = blockIdx.y * 128;
    if (row0 >= n_e) return;
    int col0 = blockIdx.x * 64;

    extern __shared__ __align__(128) char sm[];
    int* toks = (int*)sm;
    int tid = threadIdx.x, wid = tid >> 5, lane = tid & 31;
    if (tid < 128) toks[tid] = (row0 + tid < n_e) ? g_list[e * NT + row0 + tid] : -1;
    __syncthreads();
    uint32_t smb = smem_u32(sm) + 1024;

    // A slots: idx = j*256+tid; hi iff j<2 (idx<512). 4 slots/thread.
    uint32_t aoff[4]; int asz[4]; uint32_t adst[4];
#pragma unroll
    for (int j = 0; j < 4; j++) {
        int idx = j * 256 + tid, r = idx >> 2, c16 = idx & 3;
        int rr = r & 127;
        int t = toks[rr];
        asz[j] = (t >= 0) ? 16 : 0;
        aoff[j] = (uint32_t)((t < 0 ? 0 : t) * NH + c16 * 8);
        adst[j] = ((j < 2) ? 0u : 10240u) + (uint32_t)(rr * RS + c16 * 16);
    }
    // B slots: kind == j (idx>>8 == j). 4 slots/thread.
    uint32_t boff[4]; uint32_t bdst[4];
#pragma unroll
    for (int j = 0; j < 4; j++) {
        int rem = tid, r = rem >> 2, c16 = rem & 3;
        boff[j] = (uint32_t)((uint32_t)e * NI * NH + (uint32_t)(col0 + r) * NH + c16 * 8);
        bdst[j] = 20480u + (uint32_t)j * 5120u + (uint32_t)(r * RS + c16 * 16);
    }

    auto issue = [&](int ck) {
        uint32_t stg = smb + (ck & 1) * STG;
        uint32_t ko = (uint32_t)ck * 32;
        cp_async16(stg + adst[0], g_x_hi + aoff[0] + ko, asz[0]);
        cp_async16(stg + adst[1], g_x_hi + aoff[1] + ko, asz[1]);
        cp_async16(stg + adst[2], g_x_lo + aoff[2] + ko, asz[2]);
        cp_async16(stg + adst[3], g_x_lo + aoff[3] + ko, asz[3]);
        cp_async16(stg + bdst[0], g_w1_hi + boff[0] + ko, 16);
        cp_async16(stg + bdst[1], g_w1_lo + boff[1] + ko, 16);
        cp_async16(stg + bdst[2], g_w3_hi + boff[2] + ko, 16);
        cp_async16(stg + bdst[3], g_w3_lo + boff[3] + ko, 16);
        CP_COMMIT();
    };

    int m0 = (wid & 3) * 32, n0 = (wid >> 2) * 32;
    uint32_t a_off = (uint32_t)((m0 + (lane & 15)) * RS + ((lane >> 4) << 4));
    uint32_t b_off = (uint32_t)((n0 + (lane & 7) + ((lane >> 4) << 3)) * RS +
                                (((lane >> 3) & 1) << 4));

    float dg[2][4][4] = {}, du[2][4][4] = {};

    issue(0);

    const int NC = NH / 32;
#pragma unroll 1
    for (int c = 0; c < NC; c++) {
        CP_WAIT0();
        __syncthreads();
        if (c + 1 < NC) issue(c + 1);   // writes stage (c+1)&1: all its readers (iter c-1) passed barrier
        uint32_t cur = smb + (c & 1) * STG;
#pragma unroll
        for (int s2 = 0; s2 < 2; s2++) {
            uint32_t Ah[2][4], Al[2][4];
#pragma unroll
            for (int mt = 0; mt < 2; mt++) {
                ldm_x4(cur + a_off + mt * 16 * RS + s2 * 32, Ah[mt]);
                ldm_x4(cur + 10240 + a_off + mt * 16 * RS + s2 * 32, Al[mt]);
            }
            {   // w1 -> dg
                uint32_t Bh[2][4], Bl[2][4];
#pragma unroll
                for (int j = 0; j < 2; j++) {
                    ldm_x4(cur + 20480 + b_off + j * 16 * RS + s2 * 32, Bh[j]);
                    ldm_x4(cur + 25600 + b_off + j * 16 * RS + s2 * 32, Bl[j]);
                }
#pragma unroll
                for (int mt = 0; mt < 2; mt++)
#pragma unroll
                    for (int nt = 0; nt < 4; nt++) {
                        int j = nt >> 1, o = (nt & 1) * 2;
                        mma16816(dg[mt][nt], Ah[mt], Bh[j][o], Bh[j][o + 1]);
                        mma16816(dg[mt][nt], Ah[mt], Bl[j][o], Bl[j][o + 1]);
                        mma16816(dg[mt][nt], Al[mt], Bh[j][o], Bh[j][o + 1]);
                    }
            }
            {   // w3 -> du
                uint32_t Bh[2][4], Bl[2][4];
#pragma unroll
                for (int j = 0; j < 2; j++) {
                    ldm_x4(cur + 30720 + b_off + j * 16 * RS + s2 * 32, Bh[j]);
                    ldm_x4(cur + 35840 + b_off + j * 16 * RS + s2 * 32, Bl[j]);
                }
#pragma unroll
                for (int mt = 0; mt < 2; mt++)
#pragma unroll
                    for (int nt = 0; nt < 4; nt++) {
                        int j = nt >> 1, o = (nt & 1) * 2;
                        mma16816(du[mt][nt], Ah[mt], Bh[j][o], Bh[j][o + 1]);
                        mma16816(du[mt][nt], Ah[mt], Bl[j][o], Bl[j][o + 1]);
                        mma16816(du[mt][nt], Al[mt], Bh[j][o], Bh[j][o + 1]);
                    }
            }
        }
    }

    // epilogue: silu(g)*u, split to bf16 hi/lo
    int lr = lane >> 2, lc = lane & 3;
#pragma unroll
    for (int mt = 0; mt < 2; mt++)
#pragma unroll
        for (int p = 0; p < 2; p++) {
            int m = m0 + mt * 16 + lr + p * 8;
            int slot = row0 + m;
            if (slot < n_e) {
#pragma unroll
                for (int nt = 0; nt < 4; nt++) {
                    int n = col0 + n0 + nt * 8 + lc * 2;
                    float g0 = dg[mt][nt][2 * p], g1 = dg[mt][nt][2 * p + 1];
                    float u0 = du[mt][nt][2 * p], u1 = du[mt][nt][2 * p + 1];
                    float a0 = u0 * g0 / (1.f + __expf(-g0));
                    float a1 = u1 * g1 / (1.f + __expf(-g1));
                    __nv_bfloat16 h0 = __float2bfloat16_rn(a0);
                    __nv_bfloat16 h1 = __float2bfloat16_rn(a1);
                    __nv_bfloat162 hp; hp.x = h0; hp.y = h1;
                    size_t o = ((size_t)e * NT + slot) * NI + n;
                    *(uint32_t*)(g_act_hi + o) = *reinterpret_cast<uint32_t*>(&hp);
                    *(uint32_t*)(g_act_lo + o) =
                        pk2(a0 - __bfloat162float(h0), a1 - __bfloat162float(h1));
                }
            }
        }
}

// ---------------- GEMM2: out += route_w * (act * w2^T) ----------------
// 256 thr, 2 CTAs/SM. CTA 128(M)x128(N=h), K-chunk 32, 2-stage cp.async, ONE barrier/chunk.
// Warps 4(M)x2(N), warp 32x64.
__global__ __launch_bounds__(256, 2) void gemm2_mma(float* __restrict__ out) {
    int e   = blockIdx.z;
    int n_e = g_count[e];
    int row0 = blockIdx.y * 128;
    if (row0 >= n_e) return;
    int col0 = blockIdx.x * 128;

    extern __shared__ __align__(128) char sm[];
    int*   toks = (int*)sm;
    float* wts  = (float*)(sm + 512);
    int tid = threadIdx.x, wid = tid >> 5, lane = tid & 31;
    if (tid < 128) {
        int slot = row0 + tid;
        toks[tid] = (slot < n_e) ? g_list[e * NT + slot] : 0;
        wts[tid]  = (slot < n_e) ? g_wt [e * NT + slot] : 0.f;
    }
    __syncthreads();
    uint32_t smb = smem_u32(sm) + 1024;

    // A slots (act gather): hi iff j<2
    uint32_t aoff[4]; int asz[4]; uint32_t adst[4];
#pragma unroll
    for (int j = 0; j < 4; j++) {
        int idx = j * 256 + tid, r = idx >> 2, c16 = idx & 3;
        int rr = r & 127;
        int slot = row0 + rr;
        bool v = slot < n_e;
        aoff[j] = (uint32_t)((uint32_t)e * NT * NI + (uint32_t)(v ? slot : 0) * NI + c16 * 8);
        asz[j]  = v ? 16 : 0;
        adst[j] = ((j < 2) ? 0u : 10240u) + (uint32_t)(rr * RS + c16 * 16);
    }
    // B slots (w2): hi iff j<2
    uint32_t boff[4]; uint32_t bdst[4];
#pragma unroll
    for (int j = 0; j < 4; j++) {
        int idx = j * 256 + tid, r = idx >> 2, c16 = idx & 3;
        int rr = r & 127;
        boff[j] = (uint32_t)((uint32_t)e * NH * NI + (uint32_t)(col0 + rr) * NI + c16 * 8);
        bdst[j] = 20480u + ((j < 2) ? 0u : 10240u) + (uint32_t)(rr * RS + c16 * 16);
    }

    auto issue = [&](int ck) {
        uint32_t stg = smb + (ck & 1) * STG;
        uint32_t ko = (uint32_t)ck * 32;
        cp_async16(stg + adst[0], g_act_hi + aoff[0] + ko, asz[0]);
        cp_async16(stg + adst[1], g_act_hi + aoff[1] + ko, asz[1]);
        cp_async16(stg + adst[2], g_act_lo + aoff[2] + ko, asz[2]);
        cp_async16(stg + adst[3], g_act_lo + aoff[3] + ko, asz[3]);
        cp_async16(stg + bdst[0], g_w2_hi + boff[0] + ko, 16);
        cp_async16(stg + bdst[1], g_w2_hi + boff[1] + ko, 16);
        cp_async16(stg + bdst[2], g_w2_lo + boff[2] + ko, 16);
        cp_async16(stg + bdst[3], g_w2_lo + boff[3] + ko, 16);
        CP_COMMIT();
    };

    int m0 = (wid & 3) * 32, n0 = (wid >> 2) * 64;
    uint32_t a_off = (uint32_t)((m0 + (lane & 15)) * RS + ((lane >> 4) << 4));
    uint32_t b_off = (uint32_t)((n0 + (lane & 7) + ((lane >> 4) << 3)) * RS +
                                (((lane >> 3) & 1) << 4));

    float d[2][8][4] = {};

    issue(0);

    const int NC = NI / 32;
#pragma unroll 1
    for (int c = 0; c < NC; c++) {
        CP_WAIT0();
        __syncthreads();
        if (c + 1 < NC) issue(c + 1);
        uint32_t cur = smb + (c & 1) * STG;
#pragma unroll
        for (int s2 = 0; s2 < 2; s2++) {
            uint32_t Ah[2][4], Al[2][4];
#pragma unroll
            for (int mt = 0; mt < 2; mt++) {
                ldm_x4(cur + a_off + mt * 16 * RS + s2 * 32, Ah[mt]);
                ldm_x4(cur + 10240 + a_off + mt * 16 * RS + s2 * 32, Al[mt]);
            }
#pragma unroll
            for (int j = 0; j < 4; j++) {
                uint32_t Bh[4], Bl[4];
                ldm_x4(cur + 20480 + b_off + j * 16 * RS + s2 * 32, Bh);
                ldm_x4(cur + 30720 + b_off + j * 16 * RS + s2 * 32, Bl);
#pragma unroll
                for (int mt = 0; mt < 2; mt++)
#pragma unroll
                    for (int nn = 0; nn < 2; nn++) {
                        int nt = j * 2 + nn, o = nn * 2;
                        mma16816(d[mt][nt], Ah[mt], Bh[o], Bh[o + 1]);
                        mma16816(d[mt][nt], Ah[mt], Bl[o], Bl[o + 1]);
                        mma16816(d[mt][nt], Al[mt], Bh[o], Bh[o + 1]);
                    }
            }
        }
    }

    int lr = lane >> 2, lc = lane & 3;
#pragma unroll
    for (int mt = 0; mt < 2; mt++)
#pragma unroll
        for (int p = 0; p < 2; p++) {
            int m = m0 + mt * 16 + lr + p * 8;
            int slot = row0 + m;
            if (slot < n_e) {
                int   t = toks[m];
                float w = wts[m];
                float* dst = out + (size_t)t * NH;
#pragma unroll
                for (int nt = 0; nt < 8; nt++) {
                    int n = col0 + n0 + nt * 8 + lc * 2;
                    atomicAdd(dst + n,     w * d[mt][nt][2 * p]);
                    atomicAdd(dst + n + 1, w * d[mt][nt][2 * p + 1]);
                }
            }
        }
}

// ---------------- launch ----------------
extern "C" void kernel_launch(void* const* d_in, const int* in_sizes, int n_in,
                              void* d_out, int out_size) {
    const float* x  = (const float*)d_in[0];
    const float* gw = (const float*)d_in[1];
    const float* w1 = (const float*)d_in[2];
    const float* w3 = (const float*)d_in[3];
    const float* w2 = (const float*)d_in[4];
    float* out = (float*)d_out;

    const int SMEM = 1024 + 2 * STG;   // 82944 -> 2 CTAs/SM
    cudaFuncSetAttribute(gemm1_mma, cudaFuncAttributeMaxDynamicSharedMemorySize, SMEM);
    cudaFuncSetAttribute(gemm2_mma, cudaFuncAttributeMaxDynamicSharedMemorySize, SMEM);

    cudaMemsetAsync(out, 0, (size_t)out_size * sizeof(float), 0);
    // launch order: zero(0) router(1) splitx(2) splitw(3) gemm1(4) gemm2(5)
    // -> ncu (-s 5 -c 1, memset not counted) profiles gemm2
    zero_counts_kernel<<<1, 32>>>();
    router_kernel<<<(NT * 32 + 255) / 256, 256>>>(x, gw);

    const int n4x = NT * NH / 4;         // 524288
    const int n4w = NE * NI * NH / 4;    // 4194304
    splitx_kernel<<<n4x / 512, 256>>>((const float4*)x);
    dim3 gw3(n4w / 512, 3);
    splitw_kernel<<<gw3, 256>>>((const float4*)w1, (const float4*)w3, (const float4*)w2);

    dim3 grid1(NI / 64, NT / 128, NE);
    gemm1_mma<<<grid1, 256, SMEM>>>(0);

    dim3 grid2(NH / 128, NT / 128, NE);
    gemm2_mma<<<grid2, 256, SMEM>>>(out);
}